// round 13
// baseline (speedup 1.0000x reference)
#include <cuda_runtime.h>
#include <math.h>
#include <stdint.h>

#define HH 512
#define WW 512
#define BN 32
#define CN 3
#define HW (HH * WW)

#define NSETUP 512                 // setup blocks (one output row each)
#define NMAIN  (BN * HH)           // 16384 main blocks

// Scratch (allocation-free rule: __device__ globals)
__device__ float g_A[HW];          // L * 0.85
__device__ float g_Z[CN * HW];     // min(z1,z2) * 0.15
__device__ int   g_setup_done = 0;
__device__ int   g_main_done  = 0;

// ---------------------------------------------------------------------------
// Per-block fp32 closed-form homography + inverse. Cancellation-free.
// ---------------------------------------------------------------------------
__device__ __forceinline__ void solve_inline(const float* __restrict__ dst_off,
                                             int b, float M[9]) {
    float j0 = __ldg(dst_off + (b * 4 + 0) * 2 + 0), k0 = __ldg(dst_off + (b * 4 + 0) * 2 + 1);
    float j1 = __ldg(dst_off + (b * 4 + 1) * 2 + 0), k1 = __ldg(dst_off + (b * 4 + 1) * 2 + 1);
    float j2 = __ldg(dst_off + (b * 4 + 2) * 2 + 0), k2 = __ldg(dst_off + (b * 4 + 2) * 2 + 1);
    float j3 = __ldg(dst_off + (b * 4 + 3) * 2 + 0), k3 = __ldg(dst_off + (b * 4 + 3) * 2 + 1);

    float sx  = j0 - j1 + j2 - j3;
    float sy  = k0 - k1 + k2 - k3;
    float dx1 = (j1 - j2);
    float dx2 = -512.f + (j3 - j2);
    float dy1 = -512.f + (k1 - k2);
    float dy2 = (k3 - k2);
    float iden = 1.0f / (dx1 * dy2 - dx2 * dy1);
    float g = (sx * dy2 - dx2 * sy) * iden;
    float h = (dx1 * sy - sx * dy1) * iden;

    float u1 = 512.f + j1, u3 = j3;
    float v1 = k1, v3 = 512.f + k3;
    float a  = (512.f + (j1 - j0)) + g * u1;
    float bb = (j3 - j0) + h * u3;
    float c  = j0;
    float d  = (k1 - k0) + g * v1;
    float e  = (512.f + (k3 - k0)) + h * v3;
    float f  = k0;

    const float is = 1.0f / 511.0f;
    float m0 = a * is,  m1 = bb * is, m2 = c;
    float m3 = d * is,  m4 = e * is,  m5 = f;
    float m6 = g * is,  m7 = h * is,  m8 = 1.0f;

    float c00 =  (m4 * m8 - m5 * m7);
    float c01 = -(m3 * m8 - m5 * m6);
    float c02 =  (m3 * m7 - m4 * m6);
    float idet = 1.0f / (m0 * c00 + m1 * c01 + m2 * c02);

    M[0] = c00 * idet;
    M[1] = -(m1 * m8 - m2 * m7) * idet;
    M[2] =  (m1 * m5 - m2 * m4) * idet;
    M[3] = c01 * idet;
    M[4] =  (m0 * m8 - m2 * m6) * idet;
    M[5] = -(m0 * m5 - m2 * m3) * idet;
    M[6] = c02 * idet;
    M[7] = -(m0 * m7 - m1 * m6) * idet;
    M[8] =  (m0 * m4 - m1 * m3) * idet;
}

// ---------------------------------------------------------------------------
// Setup body: block s computes output row s of g_A/g_Z (thread = 4 px).
// ---------------------------------------------------------------------------
__device__ __forceinline__ void setup_body(int i, int tid,
                                           const float* __restrict__ ab,
                                           const float* __restrict__ centers,
                                           const int* __restrict__ cflag,
                                           const int* __restrict__ direction,
                                           const int* __restrict__ light_xy,
                                           const int* __restrict__ theta) {
    int j0 = tid * 4;

    float a = ab[0], bb = ab[1];
    int cf = cflag[0];
    int dk = direction[0] - 1;
    float lx = (float)light_xy[0], ly = (float)light_xy[1];
    float iml = 0.f;
    if (cf != 0) {
        float d0 = sqrtf(lx * lx + ly * ly);
        float d1 = sqrtf((lx - 255.f) * (lx - 255.f) + ly * ly);
        float d2 = sqrtf(lx * lx + (ly - 255.f) * (ly - 255.f));
        float d3 = sqrtf((lx - 512.f) * (lx - 512.f) + (ly - 512.f) * (ly - 512.f));
        iml = 1.0f / fmaxf(fmaxf(d0, d1), fmaxf(d2, d3));
    }

    const float TWO_PI = 6.283185307179586f;
    float La[4], Zv[3][4];

    #pragma unroll
    for (int q = 0; q < 4; q++) {
        int j = j0 + q;
        float L;
        if (cf == 0) {
            int tt = (dk == 0) ? i : (dk == 1) ? j : (dk == 2) ? (HH - 1 - i) : (WW - 1 - j);
            L = -((bb - a) / (float)(HH - 1)) * ((float)tt - (float)WW) + a;
        } else {
            float dx = (float)i - lx, dy = (float)j - ly;
            L = sqrtf(dx * dx + dy * dy) * iml * (a - bb) + bb;
        }
        La[q] = L * 0.85f;

        float xg = (float)(i + 1), yg = (float)(j + 1);
        #pragma unroll
        for (int k = 0; k < 3; k++) {
            float cx = centers[k * 2 + 0], cy = centers[k * 2 + 1];
            float th = (float)theta[k] * 0.017453292519943295f;
            float cth = __cosf(th), sth = __sinf(th);
            float dx = xg - cx, dy = yg - cy;
            float dist = sqrtf(dx * dx + dy * dy);
            float f1 = dist - floorf(dist);
            float t2 = cth * xg + sth * yg;
            float f2 = t2 - floorf(t2);
            float z1 = 0.5f + 0.5f * __cosf(TWO_PI * f1);
            float z2 = 0.5f + 0.5f * __cosf(TWO_PI * f2);
            Zv[k][q] = fminf(z1, z2) * 0.15f;
        }
    }

    int o = i * WW + j0;
    *(float4*)(g_A + o)          = make_float4(La[0], La[1], La[2], La[3]);
    *(float4*)(g_Z + o)          = make_float4(Zv[0][0], Zv[0][1], Zv[0][2], Zv[0][3]);
    *(float4*)(g_Z + HW + o)     = make_float4(Zv[1][0], Zv[1][1], Zv[1][2], Zv[1][3]);
    *(float4*)(g_Z + 2 * HW + o) = make_float4(Zv[2][0], Zv[2][1], Zv[2][2], Zv[2][3]);
}

// ---------------------------------------------------------------------------
// Single fused kernel. Blocks [0, NSETUP) = setup (issued first by the CTA
// scheduler). Blocks [NSETUP, NSETUP+NMAIN) = main: pair-gather + noise
// prefetch, then spin on g_setup_done (release/acquire via L2 atomics),
// then blend. Last main block resets counters for graph replay.
// ---------------------------------------------------------------------------
__global__ void __launch_bounds__(128) fused_kernel(const float* __restrict__ img,
                                                    const float* __restrict__ noise,
                                                    const float* __restrict__ dst_off,
                                                    float* __restrict__ out,
                                                    const float* __restrict__ ab,
                                                    const float* __restrict__ centers,
                                                    const int* __restrict__ cflag,
                                                    const int* __restrict__ direction,
                                                    const int* __restrict__ light_xy,
                                                    const int* __restrict__ theta) {
    int bid = blockIdx.x;
    int tid = threadIdx.x;

    if (bid < NSETUP) {
        setup_body(bid, tid, ab, centers, cflag, direction, light_xy, theta);
        __syncthreads();
        if (tid == 0) {
            __threadfence();                         // release g_A/g_Z
            atomicAdd(&g_setup_done, 1);
        }
        return;
    }

    // ---------------- main block ----------------
    __shared__ float sres[3][WW];
    int mb = bid - NSETUP;
    int b = mb & (BN - 1);      // b fast: concurrent blocks share source rows
    int y = mb >> 5;

    float M[9];
    solve_inline(dst_off, b, M);

    float fy = (float)y;
    float cA = M[1] * fy + M[2];
    float cB = M[4] * fy + M[5];
    float cC = M[7] * fy + M[8];
    const float* base = img + (size_t)b * (3 * HW);

    #pragma unroll
    for (int p = 0; p < 2; p++) {
        int x = p * 256 + 2 * tid;
        float fx0 = (float)x, fx1 = (float)(x + 1);

        float inv0 = 1.0f / (M[6] * fx0 + cC);
        float inv1 = 1.0f / (M[6] * fx1 + cC);
        float xs0 = (M[0] * fx0 + cA) * inv0;
        float ys0 = (M[3] * fx0 + cB) * inv0;
        float xs1 = (M[0] * fx1 + cA) * inv1;
        float ys1 = (M[3] * fx1 + cB) * inv1;

        float xf0 = floorf(xs0), yf0 = floorf(ys0);
        float xf1 = floorf(xs1), yf1 = floorf(ys1);
        float wx0 = xs0 - xf0, wy0 = ys0 - yf0;
        float wx1 = xs1 - xf1, wy1 = ys1 - yf1;
        int ix0 = (int)xf0, iy0 = (int)yf0;
        int ix1 = (int)xf1, iy1 = (int)yf1;

        bool adj = (iy1 == iy0) && (ix1 == ix0 + 1);

        bool vy0 = ((unsigned)iy0 < HH);
        bool vy1 = ((unsigned)(iy0 + 1) < HH);
        bool vxa = ((unsigned)ix0 < WW);
        bool vxb = ((unsigned)(ix0 + 1) < WW);
        bool vxc = ((unsigned)(ix0 + 2) < WW);

        float w000 = (1.f - wx0) * (1.f - wy0);
        float w010 = wx0 * (1.f - wy0);
        float w100 = (1.f - wx0) * wy0;
        float w110 = wx0 * wy0;
        float w001 = (1.f - wx1) * (1.f - wy1);
        float w011 = wx1 * (1.f - wy1);
        float w101 = (1.f - wx1) * wy1;
        float w111 = wx1 * wy1;

        int i0 = iy0 * WW + ix0;     // raw; only dereferenced under predicate
        int i1 = iy1 * WW + ix1;

        bool fvx0 = ((unsigned)ix1 < WW);
        bool fvx1 = ((unsigned)(ix1 + 1) < WW);
        bool fvy0 = ((unsigned)iy1 < HH);
        bool fvy1 = ((unsigned)(iy1 + 1) < HH);
        bool q00 = !adj && fvx0 && fvy0, q01 = !adj && fvx1 && fvy0;
        bool q10 = !adj && fvx0 && fvy1, q11 = !adj && fvx1 && fvy1;

        bool pa0 = vxa && vy0, pa1 = vxb && vy0, pa2 = vxc && vy0;
        bool pb0 = vxa && vy1, pb1 = vxb && vy1, pb2 = vxc && vy1;

        #pragma unroll
        for (int ch = 0; ch < 3; ch++) {
            const float* pp = base + ch * HW + i0;
            float a0 = pa0 ? __ldg(pp)          : 0.f;
            float a1 = pa1 ? __ldg(pp + 1)      : 0.f;
            float a2 = pa2 ? __ldg(pp + 2)      : 0.f;
            float b0 = pb0 ? __ldg(pp + WW)     : 0.f;
            float b1 = pb1 ? __ldg(pp + WW + 1) : 0.f;
            float b2 = pb2 ? __ldg(pp + WW + 2) : 0.f;

            float r0 = a0 * w000 + a1 * w010 + b0 * w100 + b1 * w110;

            float v00, v01, v10, v11;
            if (adj) {
                v00 = a1; v01 = a2; v10 = b1; v11 = b2;
            } else {
                const float* qq = base + ch * HW + i1;
                v00 = q00 ? __ldg(qq)          : 0.f;
                v01 = q01 ? __ldg(qq + 1)      : 0.f;
                v10 = q10 ? __ldg(qq + WW)     : 0.f;
                v11 = q11 ? __ldg(qq + WW + 1) : 0.f;
            }
            float r1 = v00 * w001 + v01 * w011 + v10 * w101 + v11 * w111;

            *(float2*)(&sres[ch][x]) = make_float2(r0, r1);
        }
    }

    // noise prefetch (independent of setup)
    int x0 = tid * 4;
    size_t o0 = ((size_t)(b * 3 + 0) * HH + y) * WW + x0;
    size_t o1 = ((size_t)(b * 3 + 1) * HH + y) * WW + x0;
    size_t o2 = ((size_t)(b * 3 + 2) * HH + y) * WW + x0;
    float4 nv0 = __ldcs((const float4*)(noise + o0));
    float4 nv1 = __ldcs((const float4*)(noise + o1));
    float4 nv2 = __ldcs((const float4*)(noise + o2));

    __syncthreads();
    if (tid == 0) {
        while (atomicAdd(&g_setup_done, 0) < NSETUP) { }   // acquire via L2
    }
    __syncthreads();

    const float kn = 0.031622776601683794f;  // sqrt(0.001)
    float4 av = *(const float4*)(g_A + (size_t)y * WW + x0);

    {
        float4 zv = *(const float4*)(g_Z + ((size_t)0 * HH + y) * WW + x0);
        float4 rv = *(const float4*)(&sres[0][x0]);
        float4 ov;
        ov.x = rv.x * av.x + zv.x + kn * nv0.x;
        ov.y = rv.y * av.y + zv.y + kn * nv0.y;
        ov.z = rv.z * av.z + zv.z + kn * nv0.z;
        ov.w = rv.w * av.w + zv.w + kn * nv0.w;
        __stcs((float4*)(out + o0), ov);
    }
    {
        float4 zv = *(const float4*)(g_Z + ((size_t)1 * HH + y) * WW + x0);
        float4 rv = *(const float4*)(&sres[1][x0]);
        float4 ov;
        ov.x = rv.x * av.x + zv.x + kn * nv1.x;
        ov.y = rv.y * av.y + zv.y + kn * nv1.y;
        ov.z = rv.z * av.z + zv.z + kn * nv1.z;
        ov.w = rv.w * av.w + zv.w + kn * nv1.w;
        __stcs((float4*)(out + o1), ov);
    }
    {
        float4 zv = *(const float4*)(g_Z + ((size_t)2 * HH + y) * WW + x0);
        float4 rv = *(const float4*)(&sres[2][x0]);
        float4 ov;
        ov.x = rv.x * av.x + zv.x + kn * nv2.x;
        ov.y = rv.y * av.y + zv.y + kn * nv2.y;
        ov.z = rv.z * av.z + zv.z + kn * nv2.z;
        ov.w = rv.w * av.w + zv.w + kn * nv2.w;
        __stcs((float4*)(out + o2), ov);
    }

    // last main block resets counters so graph replay is deterministic
    __syncthreads();
    if (tid == 0) {
        int d = atomicAdd(&g_main_done, 1);
        if (d == NMAIN - 1) {
            g_setup_done = 0;
            g_main_done = 0;
            __threadfence();
        }
    }
}

// ---------------------------------------------------------------------------
extern "C" void kernel_launch(void* const* d_in, const int* in_sizes, int n_in,
                              void* d_out, int out_size) {
    const float* image    = (const float*)d_in[0];
    const float* dst_off  = (const float*)d_in[1];
    const float* ab       = (const float*)d_in[2];
    const float* centers  = (const float*)d_in[3];
    const float* noise    = (const float*)d_in[4];
    const int*   c        = (const int*)d_in[5];
    const int*   direction= (const int*)d_in[6];
    const int*   light_xy = (const int*)d_in[7];
    const int*   theta    = (const int*)d_in[8];
    float* out = (float*)d_out;

    fused_kernel<<<NSETUP + NMAIN, 128>>>(image, noise, dst_off, out,
                                          ab, centers, c, direction,
                                          light_xy, theta);
}

// round 14
// speedup vs baseline: 1.0179x; 1.0179x over previous
#include <cuda_runtime.h>
#include <math.h>
#include <stdint.h>

#define HH 512
#define WW 512
#define BN 32
#define CN 3
#define HW (HH * WW)

// Scratch (allocation-free rule: __device__ globals)
__device__ float g_A[HW];          // L * 0.85
__device__ float g_Z[CN * HW];     // min(z1,z2) * 0.15

// ---------------------------------------------------------------------------
// Per-block fp32 closed-form homography + inverse. Cancellation-free.
// ---------------------------------------------------------------------------
__device__ __forceinline__ void solve_inline(const float* __restrict__ dst_off,
                                             int b, float M[9]) {
    float j0 = __ldg(dst_off + (b * 4 + 0) * 2 + 0), k0 = __ldg(dst_off + (b * 4 + 0) * 2 + 1);
    float j1 = __ldg(dst_off + (b * 4 + 1) * 2 + 0), k1 = __ldg(dst_off + (b * 4 + 1) * 2 + 1);
    float j2 = __ldg(dst_off + (b * 4 + 2) * 2 + 0), k2 = __ldg(dst_off + (b * 4 + 2) * 2 + 1);
    float j3 = __ldg(dst_off + (b * 4 + 3) * 2 + 0), k3 = __ldg(dst_off + (b * 4 + 3) * 2 + 1);

    float sx  = j0 - j1 + j2 - j3;
    float sy  = k0 - k1 + k2 - k3;
    float dx1 = (j1 - j2);
    float dx2 = -512.f + (j3 - j2);
    float dy1 = -512.f + (k1 - k2);
    float dy2 = (k3 - k2);
    float iden = 1.0f / (dx1 * dy2 - dx2 * dy1);
    float g = (sx * dy2 - dx2 * sy) * iden;
    float h = (dx1 * sy - sx * dy1) * iden;

    float u1 = 512.f + j1, u3 = j3;
    float v1 = k1, v3 = 512.f + k3;
    float a  = (512.f + (j1 - j0)) + g * u1;
    float bb = (j3 - j0) + h * u3;
    float c  = j0;
    float d  = (k1 - k0) + g * v1;
    float e  = (512.f + (k3 - k0)) + h * v3;
    float f  = k0;

    const float is = 1.0f / 511.0f;
    float m0 = a * is,  m1 = bb * is, m2 = c;
    float m3 = d * is,  m4 = e * is,  m5 = f;
    float m6 = g * is,  m7 = h * is,  m8 = 1.0f;

    float c00 =  (m4 * m8 - m5 * m7);
    float c01 = -(m3 * m8 - m5 * m6);
    float c02 =  (m3 * m7 - m4 * m6);
    float idet = 1.0f / (m0 * c00 + m1 * c01 + m2 * c02);

    M[0] = c00 * idet;
    M[1] = -(m1 * m8 - m2 * m7) * idet;
    M[2] =  (m1 * m5 - m2 * m4) * idet;
    M[3] = c01 * idet;
    M[4] =  (m0 * m8 - m2 * m6) * idet;
    M[5] = -(m0 * m5 - m2 * m3) * idet;
    M[6] = c02 * idet;
    M[7] = -(m0 * m7 - m1 * m6) * idet;
    M[8] =  (m0 * m4 - m1 * m3) * idet;
}

// ---------------------------------------------------------------------------
// Setup (R10 form): light mask (x0.85) + moire (x0.15); PDL trigger at top.
// ---------------------------------------------------------------------------
__global__ void setup_kernel(const float* __restrict__ ab,
                             const float* __restrict__ centers,
                             const int* __restrict__ cflag,
                             const int* __restrict__ direction,
                             const int* __restrict__ light_xy,
                             const int* __restrict__ theta) {
    cudaTriggerProgrammaticLaunchCompletion();

    int idx = blockIdx.x * blockDim.x + threadIdx.x;
    int i = idx / WW;   // row
    int j = idx % WW;   // col

    float a = ab[0], bb = ab[1];
    float L;
    if (cflag[0] == 0) {
        int k = direction[0] - 1;
        int t = (k == 0) ? i : (k == 1) ? j : (k == 2) ? (HH - 1 - i) : (WW - 1 - j);
        L = -((bb - a) / (float)(HH - 1)) * ((float)t - (float)WW) + a;
    } else {
        float x = (float)light_xy[0], y = (float)light_xy[1];
        float d0 = sqrtf(x * x + y * y);
        float d1 = sqrtf((x - 255.f) * (x - 255.f) + y * y);
        float d2 = sqrtf(x * x + (y - 255.f) * (y - 255.f));
        float d3 = sqrtf((x - 512.f) * (x - 512.f) + (y - 512.f) * (y - 512.f));
        float ml = fmaxf(fmaxf(d0, d1), fmaxf(d2, d3));
        float dx = (float)i - x, dy = (float)j - y;
        float dist = sqrtf(dx * dx + dy * dy);
        L = dist / ml * (a - bb) + bb;
    }
    g_A[idx] = L * 0.85f;

    const float TWO_PI = 6.283185307179586f;
    float xg = (float)(i + 1), yg = (float)(j + 1);
    #pragma unroll
    for (int k = 0; k < 3; k++) {
        float cx = centers[k * 2 + 0], cy = centers[k * 2 + 1];
        float th = (float)theta[k] * 0.017453292519943295f;
        float cth = __cosf(th), sth = __sinf(th);
        float dx = xg - cx, dy = yg - cy;
        float dist = sqrtf(dx * dx + dy * dy);
        float f1 = dist - floorf(dist);
        float t2 = cth * xg + sth * yg;
        float f2 = t2 - floorf(t2);
        float z1 = 0.5f + 0.5f * __cosf(TWO_PI * f1);
        float z2 = 0.5f + 0.5f * __cosf(TWO_PI * f2);
        g_Z[k * HW + idx] = fminf(z1, z2) * 0.15f;
    }
}

// ---------------------------------------------------------------------------
// generic per-pixel bilinear (fallback path, rarely active)
// ---------------------------------------------------------------------------
__device__ __forceinline__ float bilin_one(const float* __restrict__ pp0,
                                           int ix, int iy, float wx, float wy) {
    bool vx0 = ((unsigned)ix < WW);
    bool vx1 = ((unsigned)(ix + 1) < WW);
    bool vy0 = ((unsigned)iy < HH);
    bool vy1 = ((unsigned)(iy + 1) < HH);
    const float* pp = pp0 + iy * WW + ix;
    float v00 = (vx0 && vy0) ? __ldg(pp)          : 0.f;
    float v01 = (vx1 && vy0) ? __ldg(pp + 1)      : 0.f;
    float v10 = (vx0 && vy1) ? __ldg(pp + WW)     : 0.f;
    float v11 = (vx1 && vy1) ? __ldg(pp + WW + 1) : 0.f;
    return v00 * (1.f - wx) * (1.f - wy) + v01 * wx * (1.f - wy)
         + v10 * (1.f - wx) * wy + v11 * wx * wy;
}

// ---------------------------------------------------------------------------
// Fused warp + blend with 2x2 QUAD-GATHER.
// Block = 128 threads = one (b, row-pair) -> rows y0, y0+1.
// Thread t, iter p handles the quad (x, x+1) x (y0, y0+1), x = p*256 + 2t.
// When the quad maps to a 3x3 source stencil (common case), 9 loads/ch
// replace 16; predicated-zero loads reproduce border semantics exactly.
// ---------------------------------------------------------------------------
__global__ void __launch_bounds__(128) main_kernel(const float* __restrict__ img,
                                                   const float* __restrict__ noise,
                                                   const float* __restrict__ dst_off,
                                                   float* __restrict__ out) {
    __shared__ float sres[3][2][WW];

    int b = blockIdx.z;
    int y0 = blockIdx.y * 2;
    int tid = threadIdx.x;

    float M[9];
    solve_inline(dst_off, b, M);

    float fy0 = (float)y0, fy1 = (float)(y0 + 1);
    float cA0 = M[1] * fy0 + M[2], cA1 = M[1] * fy1 + M[2];
    float cB0 = M[4] * fy0 + M[5], cB1 = M[4] * fy1 + M[5];
    float cC0 = M[7] * fy0 + M[8], cC1 = M[7] * fy1 + M[8];
    const float* base = img + (size_t)b * (3 * HW);

    #pragma unroll
    for (int p = 0; p < 2; p++) {
        int x = p * 256 + 2 * tid;
        float fx0 = (float)x, fx1 = (float)(x + 1);

        // 4 pixel coords (exact reference arithmetic per pixel)
        float i00 = 1.0f / (M[6] * fx0 + cC0);
        float i10 = 1.0f / (M[6] * fx1 + cC0);
        float i01 = 1.0f / (M[6] * fx0 + cC1);
        float i11 = 1.0f / (M[6] * fx1 + cC1);
        float xs00 = (M[0] * fx0 + cA0) * i00, ys00 = (M[3] * fx0 + cB0) * i00;
        float xs10 = (M[0] * fx1 + cA0) * i10, ys10 = (M[3] * fx1 + cB0) * i10;
        float xs01 = (M[0] * fx0 + cA1) * i01, ys01 = (M[3] * fx0 + cB1) * i01;
        float xs11 = (M[0] * fx1 + cA1) * i11, ys11 = (M[3] * fx1 + cB1) * i11;

        float xf00 = floorf(xs00), yf00 = floorf(ys00);
        float xf10 = floorf(xs10), yf10 = floorf(ys10);
        float xf01 = floorf(xs01), yf01 = floorf(ys01);
        float xf11 = floorf(xs11), yf11 = floorf(ys11);
        float wx00 = xs00 - xf00, wy00 = ys00 - yf00;
        float wx10 = xs10 - xf10, wy10 = ys10 - yf10;
        float wx01 = xs01 - xf01, wy01 = ys01 - yf01;
        float wx11 = xs11 - xf11, wy11 = ys11 - yf11;
        int ix00 = (int)xf00, iy00 = (int)yf00;
        int ix10 = (int)xf10, iy10 = (int)yf10;
        int ix01 = (int)xf01, iy01 = (int)yf01;
        int ix11 = (int)xf11, iy11 = (int)yf11;

        bool quad = (ix10 == ix00 + 1) && (iy10 == iy00)
                 && (ix01 == ix00)     && (iy01 == iy00 + 1)
                 && (ix11 == ix00 + 1) && (iy11 == iy00 + 1);

        float r00, r10, r01, r11;   // per-channel results (reused)

        if (quad) {
            bool pr0 = ((unsigned)iy00 < HH);
            bool pr1 = ((unsigned)(iy00 + 1) < HH);
            bool pr2 = ((unsigned)(iy00 + 2) < HH);
            bool pc0 = ((unsigned)ix00 < WW);
            bool pc1 = ((unsigned)(ix00 + 1) < WW);
            bool pc2 = ((unsigned)(ix00 + 2) < WW);
            bool q00 = pr0 && pc0, q01 = pr0 && pc1, q02 = pr0 && pc2;
            bool q10 = pr1 && pc0, q11 = pr1 && pc1, q12 = pr1 && pc2;
            bool q20 = pr2 && pc0, q21 = pr2 && pc1, q22 = pr2 && pc2;
            int ibase = iy00 * WW + ix00;   // raw; deref only under predicate

            #pragma unroll
            for (int ch = 0; ch < 3; ch++) {
                const float* pp = base + ch * HW + ibase;
                float v00 = q00 ? __ldg(pp)              : 0.f;
                float v01 = q01 ? __ldg(pp + 1)          : 0.f;
                float v02 = q02 ? __ldg(pp + 2)          : 0.f;
                float v10 = q10 ? __ldg(pp + WW)         : 0.f;
                float v11 = q11 ? __ldg(pp + WW + 1)     : 0.f;
                float v12 = q12 ? __ldg(pp + WW + 2)     : 0.f;
                float v20 = q20 ? __ldg(pp + 2 * WW)     : 0.f;
                float v21 = q21 ? __ldg(pp + 2 * WW + 1) : 0.f;
                float v22 = q22 ? __ldg(pp + 2 * WW + 2) : 0.f;

                r00 = v00 * (1.f - wx00) * (1.f - wy00) + v01 * wx00 * (1.f - wy00)
                    + v10 * (1.f - wx00) * wy00         + v11 * wx00 * wy00;
                r10 = v01 * (1.f - wx10) * (1.f - wy10) + v02 * wx10 * (1.f - wy10)
                    + v11 * (1.f - wx10) * wy10         + v12 * wx10 * wy10;
                r01 = v10 * (1.f - wx01) * (1.f - wy01) + v11 * wx01 * (1.f - wy01)
                    + v20 * (1.f - wx01) * wy01         + v21 * wx01 * wy01;
                r11 = v11 * (1.f - wx11) * (1.f - wy11) + v12 * wx11 * (1.f - wy11)
                    + v21 * (1.f - wx11) * wy11         + v22 * wx11 * wy11;

                *(float2*)(&sres[ch][0][x]) = make_float2(r00, r10);
                *(float2*)(&sres[ch][1][x]) = make_float2(r01, r11);
            }
        } else {
            #pragma unroll
            for (int ch = 0; ch < 3; ch++) {
                const float* pp0 = base + ch * HW;
                r00 = bilin_one(pp0, ix00, iy00, wx00, wy00);
                r10 = bilin_one(pp0, ix10, iy10, wx10, wy10);
                r01 = bilin_one(pp0, ix01, iy01, wx01, wy01);
                r11 = bilin_one(pp0, ix11, iy11, wx11, wy11);
                *(float2*)(&sres[ch][0][x]) = make_float2(r00, r10);
                *(float2*)(&sres[ch][1][x]) = make_float2(r01, r11);
            }
        }
    }

    // noise row-0 prefetch (independent of setup); row-1 loads hide under
    // the row-0 blend after the barrier.
    int x0 = tid * 4;
    size_t oR0[3], oR1[3];
    #pragma unroll
    for (int ch = 0; ch < 3; ch++) {
        oR0[ch] = ((size_t)(b * 3 + ch) * HH + y0) * WW + x0;
        oR1[ch] = oR0[ch] + WW;
    }
    float4 nvA0 = __ldcs((const float4*)(noise + oR0[0]));
    float4 nvA1 = __ldcs((const float4*)(noise + oR0[1]));
    float4 nvA2 = __ldcs((const float4*)(noise + oR0[2]));

    __syncthreads();
    cudaGridDependencySynchronize();   // g_A / g_Z now visible

    const float kn = 0.031622776601683794f;  // sqrt(0.001)

    // ---- row 0 blend (noise row 1 loads issued first to overlap) ----
    float4 nvB0 = __ldcs((const float4*)(noise + oR1[0]));
    float4 nvB1 = __ldcs((const float4*)(noise + oR1[1]));
    float4 nvB2 = __ldcs((const float4*)(noise + oR1[2]));

    {
        float4 av = *(const float4*)(g_A + (size_t)y0 * WW + x0);
        float4 zv0 = *(const float4*)(g_Z + ((size_t)0 * HH + y0) * WW + x0);
        float4 zv1 = *(const float4*)(g_Z + ((size_t)1 * HH + y0) * WW + x0);
        float4 zv2 = *(const float4*)(g_Z + ((size_t)2 * HH + y0) * WW + x0);
        float4 rv0 = *(const float4*)(&sres[0][0][x0]);
        float4 rv1 = *(const float4*)(&sres[1][0][x0]);
        float4 rv2 = *(const float4*)(&sres[2][0][x0]);
        float4 ov;
        ov.x = rv0.x * av.x + zv0.x + kn * nvA0.x;
        ov.y = rv0.y * av.y + zv0.y + kn * nvA0.y;
        ov.z = rv0.z * av.z + zv0.z + kn * nvA0.z;
        ov.w = rv0.w * av.w + zv0.w + kn * nvA0.w;
        __stcs((float4*)(out + oR0[0]), ov);
        ov.x = rv1.x * av.x + zv1.x + kn * nvA1.x;
        ov.y = rv1.y * av.y + zv1.y + kn * nvA1.y;
        ov.z = rv1.z * av.z + zv1.z + kn * nvA1.z;
        ov.w = rv1.w * av.w + zv1.w + kn * nvA1.w;
        __stcs((float4*)(out + oR0[1]), ov);
        ov.x = rv2.x * av.x + zv2.x + kn * nvA2.x;
        ov.y = rv2.y * av.y + zv2.y + kn * nvA2.y;
        ov.z = rv2.z * av.z + zv2.z + kn * nvA2.z;
        ov.w = rv2.w * av.w + zv2.w + kn * nvA2.w;
        __stcs((float4*)(out + oR0[2]), ov);
    }

    // ---- row 1 blend ----
    {
        int y1 = y0 + 1;
        float4 av = *(const float4*)(g_A + (size_t)y1 * WW + x0);
        float4 zv0 = *(const float4*)(g_Z + ((size_t)0 * HH + y1) * WW + x0);
        float4 zv1 = *(const float4*)(g_Z + ((size_t)1 * HH + y1) * WW + x0);
        float4 zv2 = *(const float4*)(g_Z + ((size_t)2 * HH + y1) * WW + x0);
        float4 rv0 = *(const float4*)(&sres[0][1][x0]);
        float4 rv1 = *(const float4*)(&sres[1][1][x0]);
        float4 rv2 = *(const float4*)(&sres[2][1][x0]);
        float4 ov;
        ov.x = rv0.x * av.x + zv0.x + kn * nvB0.x;
        ov.y = rv0.y * av.y + zv0.y + kn * nvB0.y;
        ov.z = rv0.z * av.z + zv0.z + kn * nvB0.z;
        ov.w = rv0.w * av.w + zv0.w + kn * nvB0.w;
        __stcs((float4*)(out + oR1[0]), ov);
        ov.x = rv1.x * av.x + zv1.x + kn * nvB1.x;
        ov.y = rv1.y * av.y + zv1.y + kn * nvB1.y;
        ov.z = rv1.z * av.z + zv1.z + kn * nvB1.z;
        ov.w = rv1.w * av.w + zv1.w + kn * nvB1.w;
        __stcs((float4*)(out + oR1[1]), ov);
        ov.x = rv2.x * av.x + zv2.x + kn * nvB2.x;
        ov.y = rv2.y * av.y + zv2.y + kn * nvB2.y;
        ov.z = rv2.z * av.z + zv2.z + kn * nvB2.z;
        ov.w = rv2.w * av.w + zv2.w + kn * nvB2.w;
        __stcs((float4*)(out + oR1[2]), ov);
    }
}

// ---------------------------------------------------------------------------
extern "C" void kernel_launch(void* const* d_in, const int* in_sizes, int n_in,
                              void* d_out, int out_size) {
    const float* image    = (const float*)d_in[0];
    const float* dst_off  = (const float*)d_in[1];
    const float* ab       = (const float*)d_in[2];
    const float* centers  = (const float*)d_in[3];
    const float* noise    = (const float*)d_in[4];
    const int*   c        = (const int*)d_in[5];
    const int*   direction= (const int*)d_in[6];
    const int*   light_xy = (const int*)d_in[7];
    const int*   theta    = (const int*)d_in[8];
    float* out = (float*)d_out;

    setup_kernel<<<HW / 256, 256>>>(ab, centers, c, direction, light_xy, theta);

    cudaLaunchConfig_t cfg = {};
    cfg.gridDim = dim3(1, HH / 2, BN);
    cfg.blockDim = dim3(128, 1, 1);
    cfg.dynamicSmemBytes = 0;
    cfg.stream = 0;
    cudaLaunchAttribute attr[1];
    attr[0].id = cudaLaunchAttributeProgrammaticStreamSerialization;
    attr[0].val.programmaticStreamSerializationAllowed = 1;
    cfg.attrs = attr;
    cfg.numAttrs = 1;
    cudaLaunchKernelEx(&cfg, main_kernel, image, noise, dst_off, out);
}

// round 15
// speedup vs baseline: 1.0830x; 1.0640x over previous
#include <cuda_runtime.h>
#include <math.h>
#include <stdint.h>

#define HH 512
#define WW 512
#define BN 32
#define CN 3
#define HW (HH * WW)

// Scratch (allocation-free rule: __device__ globals)
__device__ float g_A[HW];          // L * 0.85
__device__ float g_Z[CN * HW];     // min(z1,z2) * 0.15

// ---------------------------------------------------------------------------
// Per-block fp32 closed-form homography + inverse. Cancellation-free.
// ---------------------------------------------------------------------------
__device__ __forceinline__ void solve_inline(const float* __restrict__ dst_off,
                                             int b, float M[9]) {
    float j0 = __ldg(dst_off + (b * 4 + 0) * 2 + 0), k0 = __ldg(dst_off + (b * 4 + 0) * 2 + 1);
    float j1 = __ldg(dst_off + (b * 4 + 1) * 2 + 0), k1 = __ldg(dst_off + (b * 4 + 1) * 2 + 1);
    float j2 = __ldg(dst_off + (b * 4 + 2) * 2 + 0), k2 = __ldg(dst_off + (b * 4 + 2) * 2 + 1);
    float j3 = __ldg(dst_off + (b * 4 + 3) * 2 + 0), k3 = __ldg(dst_off + (b * 4 + 3) * 2 + 1);

    float sx  = j0 - j1 + j2 - j3;
    float sy  = k0 - k1 + k2 - k3;
    float dx1 = (j1 - j2);
    float dx2 = -512.f + (j3 - j2);
    float dy1 = -512.f + (k1 - k2);
    float dy2 = (k3 - k2);
    float iden = 1.0f / (dx1 * dy2 - dx2 * dy1);
    float g = (sx * dy2 - dx2 * sy) * iden;
    float h = (dx1 * sy - sx * dy1) * iden;

    float u1 = 512.f + j1, u3 = j3;
    float v1 = k1, v3 = 512.f + k3;
    float a  = (512.f + (j1 - j0)) + g * u1;
    float bb = (j3 - j0) + h * u3;
    float c  = j0;
    float d  = (k1 - k0) + g * v1;
    float e  = (512.f + (k3 - k0)) + h * v3;
    float f  = k0;

    const float is = 1.0f / 511.0f;
    float m0 = a * is,  m1 = bb * is, m2 = c;
    float m3 = d * is,  m4 = e * is,  m5 = f;
    float m6 = g * is,  m7 = h * is,  m8 = 1.0f;

    float c00 =  (m4 * m8 - m5 * m7);
    float c01 = -(m3 * m8 - m5 * m6);
    float c02 =  (m3 * m7 - m4 * m6);
    float idet = 1.0f / (m0 * c00 + m1 * c01 + m2 * c02);

    M[0] = c00 * idet;
    M[1] = -(m1 * m8 - m2 * m7) * idet;
    M[2] =  (m1 * m5 - m2 * m4) * idet;
    M[3] = c01 * idet;
    M[4] =  (m0 * m8 - m2 * m6) * idet;
    M[5] = -(m0 * m5 - m2 * m3) * idet;
    M[6] = c02 * idet;
    M[7] = -(m0 * m7 - m1 * m6) * idet;
    M[8] =  (m0 * m4 - m1 * m3) * idet;
}

// ---------------------------------------------------------------------------
// Setup (R10 form): light mask (x0.85) + moire (x0.15); PDL trigger at top.
// ---------------------------------------------------------------------------
__global__ void setup_kernel(const float* __restrict__ ab,
                             const float* __restrict__ centers,
                             const int* __restrict__ cflag,
                             const int* __restrict__ direction,
                             const int* __restrict__ light_xy,
                             const int* __restrict__ theta) {
    cudaTriggerProgrammaticLaunchCompletion();

    int idx = blockIdx.x * blockDim.x + threadIdx.x;
    int i = idx / WW;   // row
    int j = idx % WW;   // col

    float a = ab[0], bb = ab[1];
    float L;
    if (cflag[0] == 0) {
        int k = direction[0] - 1;
        int t = (k == 0) ? i : (k == 1) ? j : (k == 2) ? (HH - 1 - i) : (WW - 1 - j);
        L = -((bb - a) / (float)(HH - 1)) * ((float)t - (float)WW) + a;
    } else {
        float x = (float)light_xy[0], y = (float)light_xy[1];
        float d0 = sqrtf(x * x + y * y);
        float d1 = sqrtf((x - 255.f) * (x - 255.f) + y * y);
        float d2 = sqrtf(x * x + (y - 255.f) * (y - 255.f));
        float d3 = sqrtf((x - 512.f) * (x - 512.f) + (y - 512.f) * (y - 512.f));
        float ml = fmaxf(fmaxf(d0, d1), fmaxf(d2, d3));
        float dx = (float)i - x, dy = (float)j - y;
        float dist = sqrtf(dx * dx + dy * dy);
        L = dist / ml * (a - bb) + bb;
    }
    g_A[idx] = L * 0.85f;

    const float TWO_PI = 6.283185307179586f;
    float xg = (float)(i + 1), yg = (float)(j + 1);
    #pragma unroll
    for (int k = 0; k < 3; k++) {
        float cx = centers[k * 2 + 0], cy = centers[k * 2 + 1];
        float th = (float)theta[k] * 0.017453292519943295f;
        float cth = __cosf(th), sth = __sinf(th);
        float dx = xg - cx, dy = yg - cy;
        float dist = sqrtf(dx * dx + dy * dy);
        float f1 = dist - floorf(dist);
        float t2 = cth * xg + sth * yg;
        float f2 = t2 - floorf(t2);
        float z1 = 0.5f + 0.5f * __cosf(TWO_PI * f1);
        float z2 = 0.5f + 0.5f * __cosf(TWO_PI * f2);
        g_Z[k * HW + idx] = fminf(z1, z2) * 0.15f;
    }
}

// ---------------------------------------------------------------------------
// Fused warp + blend, pair-gather, NO SMEM / NO BARRIER.
// Block = 128 threads = one (b, y) row. Thread t, iter p: pixels
// x = p*256 + 2t, x+1. Gather results held in registers; blend runs in the
// same (pair) laning with float2 streaming accesses (aligned: x even).
// Interior fast path (~99% of pairs, warp-uniform) skips all predicates.
// ---------------------------------------------------------------------------
__global__ void __launch_bounds__(128) main_kernel(const float* __restrict__ img,
                                                   const float* __restrict__ noise,
                                                   const float* __restrict__ dst_off,
                                                   float* __restrict__ out) {
    int b = blockIdx.z;
    int y = blockIdx.y;
    int tid = threadIdx.x;

    float M[9];
    solve_inline(dst_off, b, M);

    float fy = (float)y;
    float cA = M[1] * fy + M[2];
    float cB = M[4] * fy + M[5];
    float cC = M[7] * fy + M[8];
    const float* base = img + (size_t)b * (3 * HW);

    float rr[2][3][2];   // [p][ch][pix] gather results, live across the loop

    #pragma unroll
    for (int p = 0; p < 2; p++) {
        int x = p * 256 + 2 * tid;
        float fx0 = (float)x, fx1 = (float)(x + 1);

        float inv0 = 1.0f / (M[6] * fx0 + cC);
        float inv1 = 1.0f / (M[6] * fx1 + cC);
        float xs0 = (M[0] * fx0 + cA) * inv0;
        float ys0 = (M[3] * fx0 + cB) * inv0;
        float xs1 = (M[0] * fx1 + cA) * inv1;
        float ys1 = (M[3] * fx1 + cB) * inv1;

        float xf0 = floorf(xs0), yf0 = floorf(ys0);
        float xf1 = floorf(xs1), yf1 = floorf(ys1);
        float wx0 = xs0 - xf0, wy0 = ys0 - yf0;
        float wx1 = xs1 - xf1, wy1 = ys1 - yf1;
        int ix0 = (int)xf0, iy0 = (int)yf0;
        int ix1 = (int)xf1, iy1 = (int)yf1;

        bool adj = (iy1 == iy0) && (ix1 == ix0 + 1);
        bool interior = adj && ((unsigned)ix0 < (WW - 2)) && ((unsigned)iy0 < (HH - 1));

        float w000 = (1.f - wx0) * (1.f - wy0);
        float w010 = wx0 * (1.f - wy0);
        float w100 = (1.f - wx0) * wy0;
        float w110 = wx0 * wy0;
        float w001 = (1.f - wx1) * (1.f - wy1);
        float w011 = wx1 * (1.f - wy1);
        float w101 = (1.f - wx1) * wy1;
        float w111 = wx1 * wy1;

        int i0 = iy0 * WW + ix0;

        if (interior) {
            // no predicates, 6 raw loads per channel
            #pragma unroll
            for (int ch = 0; ch < 3; ch++) {
                const float* pp = base + ch * HW + i0;
                float a0 = __ldg(pp);
                float a1 = __ldg(pp + 1);
                float a2 = __ldg(pp + 2);
                float b0 = __ldg(pp + WW);
                float b1 = __ldg(pp + WW + 1);
                float b2 = __ldg(pp + WW + 2);
                rr[p][ch][0] = a0 * w000 + a1 * w010 + b0 * w100 + b1 * w110;
                rr[p][ch][1] = a1 * w001 + a2 * w011 + b1 * w101 + b2 * w111;
            }
        } else {
            // border / non-adjacent: fully predicated generic path
            bool vy0 = ((unsigned)iy0 < HH);
            bool vy1 = ((unsigned)(iy0 + 1) < HH);
            bool vxa = ((unsigned)ix0 < WW);
            bool vxb = ((unsigned)(ix0 + 1) < WW);
            bool gy0 = ((unsigned)iy1 < HH);
            bool gy1 = ((unsigned)(iy1 + 1) < HH);
            bool gxa = ((unsigned)ix1 < WW);
            bool gxb = ((unsigned)(ix1 + 1) < WW);
            int i1 = iy1 * WW + ix1;
            bool p00 = vxa && vy0, p01 = vxb && vy0;
            bool p10 = vxa && vy1, p11 = vxb && vy1;
            bool q00 = gxa && gy0, q01 = gxb && gy0;
            bool q10 = gxa && gy1, q11 = gxb && gy1;
            #pragma unroll
            for (int ch = 0; ch < 3; ch++) {
                const float* pp = base + ch * HW + i0;
                const float* qq = base + ch * HW + i1;
                float v00 = p00 ? __ldg(pp)          : 0.f;
                float v01 = p01 ? __ldg(pp + 1)      : 0.f;
                float v10 = p10 ? __ldg(pp + WW)     : 0.f;
                float v11 = p11 ? __ldg(pp + WW + 1) : 0.f;
                float u00 = q00 ? __ldg(qq)          : 0.f;
                float u01 = q01 ? __ldg(qq + 1)      : 0.f;
                float u10 = q10 ? __ldg(qq + WW)     : 0.f;
                float u11 = q11 ? __ldg(qq + WW + 1) : 0.f;
                rr[p][ch][0] = v00 * w000 + v01 * w010 + v10 * w100 + v11 * w110;
                rr[p][ch][1] = u00 * w001 + u01 * w011 + u10 * w101 + u11 * w111;
            }
        }
    }

    // noise p=0 prefetch (independent of setup) — hides under the PDL wait
    int xA = 2 * tid;          // p=0 pair
    int xB = 256 + 2 * tid;    // p=1 pair
    size_t rowoff = (size_t)(b * 3) * HW + (size_t)y * WW;
    float2 nA0 = __ldcs((const float2*)(noise + rowoff + xA));
    float2 nA1 = __ldcs((const float2*)(noise + rowoff + HW + xA));
    float2 nA2 = __ldcs((const float2*)(noise + rowoff + 2 * HW + xA));

    cudaGridDependencySynchronize();   // g_A / g_Z now visible

    const float kn = 0.031622776601683794f;  // sqrt(0.001)
    size_t arow = (size_t)y * WW;
    size_t zrow = (size_t)y * WW;

    // p=1 noise issued first so its latency hides under the p=0 blend
    float2 nB0 = __ldcs((const float2*)(noise + rowoff + xB));
    float2 nB1 = __ldcs((const float2*)(noise + rowoff + HW + xB));
    float2 nB2 = __ldcs((const float2*)(noise + rowoff + 2 * HW + xB));

    // ---- p = 0 blend ----
    {
        float2 av = *(const float2*)(g_A + arow + xA);
        float2 z0 = *(const float2*)(g_Z + zrow + xA);
        float2 z1 = *(const float2*)(g_Z + HW + zrow + xA);
        float2 z2 = *(const float2*)(g_Z + 2 * HW + zrow + xA);
        float2 ov;
        ov.x = rr[0][0][0] * av.x + z0.x + kn * nA0.x;
        ov.y = rr[0][0][1] * av.y + z0.y + kn * nA0.y;
        __stcs((float2*)(out + rowoff + xA), ov);
        ov.x = rr[0][1][0] * av.x + z1.x + kn * nA1.x;
        ov.y = rr[0][1][1] * av.y + z1.y + kn * nA1.y;
        __stcs((float2*)(out + rowoff + HW + xA), ov);
        ov.x = rr[0][2][0] * av.x + z2.x + kn * nA2.x;
        ov.y = rr[0][2][1] * av.y + z2.y + kn * nA2.y;
        __stcs((float2*)(out + rowoff + 2 * HW + xA), ov);
    }

    // ---- p = 1 blend ----
    {
        float2 av = *(const float2*)(g_A + arow + xB);
        float2 z0 = *(const float2*)(g_Z + zrow + xB);
        float2 z1 = *(const float2*)(g_Z + HW + zrow + xB);
        float2 z2 = *(const float2*)(g_Z + 2 * HW + zrow + xB);
        float2 ov;
        ov.x = rr[1][0][0] * av.x + z0.x + kn * nB0.x;
        ov.y = rr[1][0][1] * av.y + z0.y + kn * nB0.y;
        __stcs((float2*)(out + rowoff + xB), ov);
        ov.x = rr[1][1][0] * av.x + z1.x + kn * nB1.x;
        ov.y = rr[1][1][1] * av.y + z1.y + kn * nB1.y;
        __stcs((float2*)(out + rowoff + HW + xB), ov);
        ov.x = rr[1][2][0] * av.x + z2.x + kn * nB2.x;
        ov.y = rr[1][2][1] * av.y + z2.y + kn * nB2.y;
        __stcs((float2*)(out + rowoff + 2 * HW + xB), ov);
    }
}

// ---------------------------------------------------------------------------
extern "C" void kernel_launch(void* const* d_in, const int* in_sizes, int n_in,
                              void* d_out, int out_size) {
    const float* image    = (const float*)d_in[0];
    const float* dst_off  = (const float*)d_in[1];
    const float* ab       = (const float*)d_in[2];
    const float* centers  = (const float*)d_in[3];
    const float* noise    = (const float*)d_in[4];
    const int*   c        = (const int*)d_in[5];
    const int*   direction= (const int*)d_in[6];
    const int*   light_xy = (const int*)d_in[7];
    const int*   theta    = (const int*)d_in[8];
    float* out = (float*)d_out;

    setup_kernel<<<HW / 256, 256>>>(ab, centers, c, direction, light_xy, theta);

    cudaLaunchConfig_t cfg = {};
    cfg.gridDim = dim3(1, HH, BN);
    cfg.blockDim = dim3(128, 1, 1);
    cfg.dynamicSmemBytes = 0;
    cfg.stream = 0;
    cudaLaunchAttribute attr[1];
    attr[0].id = cudaLaunchAttributeProgrammaticStreamSerialization;
    attr[0].val.programmaticStreamSerializationAllowed = 1;
    cfg.attrs = attr;
    cfg.numAttrs = 1;
    cudaLaunchKernelEx(&cfg, main_kernel, image, noise, dst_off, out);
}

// round 16
// speedup vs baseline: 1.1270x; 1.0406x over previous
#include <cuda_runtime.h>
#include <math.h>
#include <stdint.h>

#define HH 512
#define WW 512
#define BN 32
#define CN 3
#define HW (HH * WW)

// Scratch (allocation-free rule: __device__ globals)
__device__ float g_A[HW];          // L * 0.85
__device__ float g_Z[CN * HW];     // min(z1,z2) * 0.15

// ---------------------------------------------------------------------------
// Per-block fp32 closed-form homography + inverse. Cancellation-free.
// ---------------------------------------------------------------------------
__device__ __forceinline__ void solve_inline(const float* __restrict__ dst_off,
                                             int b, float M[9]) {
    float j0 = __ldg(dst_off + (b * 4 + 0) * 2 + 0), k0 = __ldg(dst_off + (b * 4 + 0) * 2 + 1);
    float j1 = __ldg(dst_off + (b * 4 + 1) * 2 + 0), k1 = __ldg(dst_off + (b * 4 + 1) * 2 + 1);
    float j2 = __ldg(dst_off + (b * 4 + 2) * 2 + 0), k2 = __ldg(dst_off + (b * 4 + 2) * 2 + 1);
    float j3 = __ldg(dst_off + (b * 4 + 3) * 2 + 0), k3 = __ldg(dst_off + (b * 4 + 3) * 2 + 1);

    float sx  = j0 - j1 + j2 - j3;
    float sy  = k0 - k1 + k2 - k3;
    float dx1 = (j1 - j2);
    float dx2 = -512.f + (j3 - j2);
    float dy1 = -512.f + (k1 - k2);
    float dy2 = (k3 - k2);
    float iden = 1.0f / (dx1 * dy2 - dx2 * dy1);
    float g = (sx * dy2 - dx2 * sy) * iden;
    float h = (dx1 * sy - sx * dy1) * iden;

    float u1 = 512.f + j1, u3 = j3;
    float v1 = k1, v3 = 512.f + k3;
    float a  = (512.f + (j1 - j0)) + g * u1;
    float bb = (j3 - j0) + h * u3;
    float c  = j0;
    float d  = (k1 - k0) + g * v1;
    float e  = (512.f + (k3 - k0)) + h * v3;
    float f  = k0;

    const float is = 1.0f / 511.0f;
    float m0 = a * is,  m1 = bb * is, m2 = c;
    float m3 = d * is,  m4 = e * is,  m5 = f;
    float m6 = g * is,  m7 = h * is,  m8 = 1.0f;

    float c00 =  (m4 * m8 - m5 * m7);
    float c01 = -(m3 * m8 - m5 * m6);
    float c02 =  (m3 * m7 - m4 * m6);
    float idet = 1.0f / (m0 * c00 + m1 * c01 + m2 * c02);

    M[0] = c00 * idet;
    M[1] = -(m1 * m8 - m2 * m7) * idet;
    M[2] =  (m1 * m5 - m2 * m4) * idet;
    M[3] = c01 * idet;
    M[4] =  (m0 * m8 - m2 * m6) * idet;
    M[5] = -(m0 * m5 - m2 * m3) * idet;
    M[6] = c02 * idet;
    M[7] = -(m0 * m7 - m1 * m6) * idet;
    M[8] =  (m0 * m4 - m1 * m3) * idet;
}

// ---------------------------------------------------------------------------
// Setup (R10 form): light mask (x0.85) + moire (x0.15); PDL trigger at top.
// ---------------------------------------------------------------------------
__global__ void setup_kernel(const float* __restrict__ ab,
                             const float* __restrict__ centers,
                             const int* __restrict__ cflag,
                             const int* __restrict__ direction,
                             const int* __restrict__ light_xy,
                             const int* __restrict__ theta) {
    cudaTriggerProgrammaticLaunchCompletion();

    int idx = blockIdx.x * blockDim.x + threadIdx.x;
    int i = idx / WW;   // row
    int j = idx % WW;   // col

    float a = ab[0], bb = ab[1];
    float L;
    if (cflag[0] == 0) {
        int k = direction[0] - 1;
        int t = (k == 0) ? i : (k == 1) ? j : (k == 2) ? (HH - 1 - i) : (WW - 1 - j);
        L = -((bb - a) / (float)(HH - 1)) * ((float)t - (float)WW) + a;
    } else {
        float x = (float)light_xy[0], y = (float)light_xy[1];
        float d0 = sqrtf(x * x + y * y);
        float d1 = sqrtf((x - 255.f) * (x - 255.f) + y * y);
        float d2 = sqrtf(x * x + (y - 255.f) * (y - 255.f));
        float d3 = sqrtf((x - 512.f) * (x - 512.f) + (y - 512.f) * (y - 512.f));
        float ml = fmaxf(fmaxf(d0, d1), fmaxf(d2, d3));
        float dx = (float)i - x, dy = (float)j - y;
        float dist = sqrtf(dx * dx + dy * dy);
        L = dist / ml * (a - bb) + bb;
    }
    g_A[idx] = L * 0.85f;

    const float TWO_PI = 6.283185307179586f;
    float xg = (float)(i + 1), yg = (float)(j + 1);
    #pragma unroll
    for (int k = 0; k < 3; k++) {
        float cx = centers[k * 2 + 0], cy = centers[k * 2 + 1];
        float th = (float)theta[k] * 0.017453292519943295f;
        float cth = __cosf(th), sth = __sinf(th);
        float dx = xg - cx, dy = yg - cy;
        float dist = sqrtf(dx * dx + dy * dy);
        float f1 = dist - floorf(dist);
        float t2 = cth * xg + sth * yg;
        float f2 = t2 - floorf(t2);
        float z1 = 0.5f + 0.5f * __cosf(TWO_PI * f1);
        float z2 = 0.5f + 0.5f * __cosf(TWO_PI * f2);
        g_Z[k * HW + idx] = fminf(z1, z2) * 0.15f;
    }
}

// ---------------------------------------------------------------------------
// Fused warp + blend, pair-gather, no smem/barrier, NO P-LOOP.
// Block = 256 threads = one (b, y) row; thread t owns pixels 2t, 2t+1.
// All 18 gather + 6 noise loads issue as one batch (max MLP, minimal regs).
// Interior fast path (~99% of pairs) skips all predicates.
// ---------------------------------------------------------------------------
__global__ void __launch_bounds__(256) main_kernel(const float* __restrict__ img,
                                                   const float* __restrict__ noise,
                                                   const float* __restrict__ dst_off,
                                                   float* __restrict__ out) {
    int b = blockIdx.z;
    int y = blockIdx.y;
    int tid = threadIdx.x;
    int x = 2 * tid;

    float M[9];
    solve_inline(dst_off, b, M);

    float fy = (float)y;
    float cA = M[1] * fy + M[2];
    float cB = M[4] * fy + M[5];
    float cC = M[7] * fy + M[8];
    const float* base = img + (size_t)b * (3 * HW);

    float fx0 = (float)x, fx1 = (float)(x + 1);
    float inv0 = 1.0f / (M[6] * fx0 + cC);
    float inv1 = 1.0f / (M[6] * fx1 + cC);
    float xs0 = (M[0] * fx0 + cA) * inv0;
    float ys0 = (M[3] * fx0 + cB) * inv0;
    float xs1 = (M[0] * fx1 + cA) * inv1;
    float ys1 = (M[3] * fx1 + cB) * inv1;

    float xf0 = floorf(xs0), yf0 = floorf(ys0);
    float xf1 = floorf(xs1), yf1 = floorf(ys1);
    float wx0 = xs0 - xf0, wy0 = ys0 - yf0;
    float wx1 = xs1 - xf1, wy1 = ys1 - yf1;
    int ix0 = (int)xf0, iy0 = (int)yf0;
    int ix1 = (int)xf1, iy1 = (int)yf1;

    bool adj = (iy1 == iy0) && (ix1 == ix0 + 1);
    bool interior = adj && ((unsigned)ix0 < (WW - 2)) && ((unsigned)iy0 < (HH - 1));

    float w000 = (1.f - wx0) * (1.f - wy0);
    float w010 = wx0 * (1.f - wy0);
    float w100 = (1.f - wx0) * wy0;
    float w110 = wx0 * wy0;
    float w001 = (1.f - wx1) * (1.f - wy1);
    float w011 = wx1 * (1.f - wy1);
    float w101 = (1.f - wx1) * wy1;
    float w111 = wx1 * wy1;

    int i0 = iy0 * WW + ix0;

    float rr[3][2];   // [ch][pix]

    if (interior) {
        #pragma unroll
        for (int ch = 0; ch < 3; ch++) {
            const float* pp = base + ch * HW + i0;
            float a0 = __ldg(pp);
            float a1 = __ldg(pp + 1);
            float a2 = __ldg(pp + 2);
            float b0 = __ldg(pp + WW);
            float b1 = __ldg(pp + WW + 1);
            float b2 = __ldg(pp + WW + 2);
            rr[ch][0] = a0 * w000 + a1 * w010 + b0 * w100 + b1 * w110;
            rr[ch][1] = a1 * w001 + a2 * w011 + b1 * w101 + b2 * w111;
        }
    } else {
        bool vy0 = ((unsigned)iy0 < HH);
        bool vy1 = ((unsigned)(iy0 + 1) < HH);
        bool vxa = ((unsigned)ix0 < WW);
        bool vxb = ((unsigned)(ix0 + 1) < WW);
        bool gy0 = ((unsigned)iy1 < HH);
        bool gy1 = ((unsigned)(iy1 + 1) < HH);
        bool gxa = ((unsigned)ix1 < WW);
        bool gxb = ((unsigned)(ix1 + 1) < WW);
        int i1 = iy1 * WW + ix1;
        bool p00 = vxa && vy0, p01 = vxb && vy0;
        bool p10 = vxa && vy1, p11 = vxb && vy1;
        bool q00 = gxa && gy0, q01 = gxb && gy0;
        bool q10 = gxa && gy1, q11 = gxb && gy1;
        #pragma unroll
        for (int ch = 0; ch < 3; ch++) {
            const float* pp = base + ch * HW + i0;
            const float* qq = base + ch * HW + i1;
            float v00 = p00 ? __ldg(pp)          : 0.f;
            float v01 = p01 ? __ldg(pp + 1)      : 0.f;
            float v10 = p10 ? __ldg(pp + WW)     : 0.f;
            float v11 = p11 ? __ldg(pp + WW + 1) : 0.f;
            float u00 = q00 ? __ldg(qq)          : 0.f;
            float u01 = q01 ? __ldg(qq + 1)      : 0.f;
            float u10 = q10 ? __ldg(qq + WW)     : 0.f;
            float u11 = q11 ? __ldg(qq + WW + 1) : 0.f;
            rr[ch][0] = v00 * w000 + v01 * w010 + v10 * w100 + v11 * w110;
            rr[ch][1] = u00 * w001 + u01 * w011 + u10 * w101 + u11 * w111;
        }
    }

    // noise prefetch (independent of setup) — hides under the PDL wait
    size_t rowoff = (size_t)(b * 3) * HW + (size_t)y * WW;
    float2 n0 = __ldcs((const float2*)(noise + rowoff + x));
    float2 n1 = __ldcs((const float2*)(noise + rowoff + HW + x));
    float2 n2 = __ldcs((const float2*)(noise + rowoff + 2 * HW + x));

    cudaGridDependencySynchronize();   // g_A / g_Z now visible

    const float kn = 0.031622776601683794f;  // sqrt(0.001)
    size_t prow = (size_t)y * WW + x;

    float2 av = *(const float2*)(g_A + prow);
    float2 z0 = *(const float2*)(g_Z + prow);
    float2 z1 = *(const float2*)(g_Z + HW + prow);
    float2 z2 = *(const float2*)(g_Z + 2 * HW + prow);

    float2 ov;
    ov.x = rr[0][0] * av.x + z0.x + kn * n0.x;
    ov.y = rr[0][1] * av.y + z0.y + kn * n0.y;
    __stcs((float2*)(out + rowoff + x), ov);
    ov.x = rr[1][0] * av.x + z1.x + kn * n1.x;
    ov.y = rr[1][1] * av.y + z1.y + kn * n1.y;
    __stcs((float2*)(out + rowoff + HW + x), ov);
    ov.x = rr[2][0] * av.x + z2.x + kn * n2.x;
    ov.y = rr[2][1] * av.y + z2.y + kn * n2.y;
    __stcs((float2*)(out + rowoff + 2 * HW + x), ov);
}

// ---------------------------------------------------------------------------
extern "C" void kernel_launch(void* const* d_in, const int* in_sizes, int n_in,
                              void* d_out, int out_size) {
    const float* image    = (const float*)d_in[0];
    const float* dst_off  = (const float*)d_in[1];
    const float* ab       = (const float*)d_in[2];
    const float* centers  = (const float*)d_in[3];
    const float* noise    = (const float*)d_in[4];
    const int*   c        = (const int*)d_in[5];
    const int*   direction= (const int*)d_in[6];
    const int*   light_xy = (const int*)d_in[7];
    const int*   theta    = (const int*)d_in[8];
    float* out = (float*)d_out;

    setup_kernel<<<HW / 256, 256>>>(ab, centers, c, direction, light_xy, theta);

    cudaLaunchConfig_t cfg = {};
    cfg.gridDim = dim3(1, HH, BN);
    cfg.blockDim = dim3(256, 1, 1);
    cfg.dynamicSmemBytes = 0;
    cfg.stream = 0;
    cudaLaunchAttribute attr[1];
    attr[0].id = cudaLaunchAttributeProgrammaticStreamSerialization;
    attr[0].val.programmaticStreamSerializationAllowed = 1;
    cfg.attrs = attr;
    cfg.numAttrs = 1;
    cudaLaunchKernelEx(&cfg, main_kernel, image, noise, dst_off, out);
}

// round 17
// speedup vs baseline: 1.1645x; 1.0333x over previous
#include <cuda_runtime.h>
#include <math.h>
#include <stdint.h>

#define HH 512
#define WW 512
#define BN 32
#define CN 3
#define HW (HH * WW)

// Scratch (allocation-free rule: __device__ globals)
__device__ float g_A[HW];          // L * 0.85
__device__ float g_Z[CN * HW];     // min(z1,z2) * 0.15

// ---------------------------------------------------------------------------
// fp32 closed-form homography + inverse. Cancellation-free. Runs on ONE
// thread per block; result broadcast through smem.
// ---------------------------------------------------------------------------
__device__ __forceinline__ void solve_one_thread(const float* __restrict__ dst_off,
                                                 int b, float* __restrict__ sM) {
    float j0 = __ldg(dst_off + (b * 4 + 0) * 2 + 0), k0 = __ldg(dst_off + (b * 4 + 0) * 2 + 1);
    float j1 = __ldg(dst_off + (b * 4 + 1) * 2 + 0), k1 = __ldg(dst_off + (b * 4 + 1) * 2 + 1);
    float j2 = __ldg(dst_off + (b * 4 + 2) * 2 + 0), k2 = __ldg(dst_off + (b * 4 + 2) * 2 + 1);
    float j3 = __ldg(dst_off + (b * 4 + 3) * 2 + 0), k3 = __ldg(dst_off + (b * 4 + 3) * 2 + 1);

    float sx  = j0 - j1 + j2 - j3;
    float sy  = k0 - k1 + k2 - k3;
    float dx1 = (j1 - j2);
    float dx2 = -512.f + (j3 - j2);
    float dy1 = -512.f + (k1 - k2);
    float dy2 = (k3 - k2);
    float iden = 1.0f / (dx1 * dy2 - dx2 * dy1);
    float g = (sx * dy2 - dx2 * sy) * iden;
    float h = (dx1 * sy - sx * dy1) * iden;

    float u1 = 512.f + j1, u3 = j3;
    float v1 = k1, v3 = 512.f + k3;
    float a  = (512.f + (j1 - j0)) + g * u1;
    float bb = (j3 - j0) + h * u3;
    float c  = j0;
    float d  = (k1 - k0) + g * v1;
    float e  = (512.f + (k3 - k0)) + h * v3;
    float f  = k0;

    const float is = 1.0f / 511.0f;
    float m0 = a * is,  m1 = bb * is, m2 = c;
    float m3 = d * is,  m4 = e * is,  m5 = f;
    float m6 = g * is,  m7 = h * is,  m8 = 1.0f;

    float c00 =  (m4 * m8 - m5 * m7);
    float c01 = -(m3 * m8 - m5 * m6);
    float c02 =  (m3 * m7 - m4 * m6);
    float idet = 1.0f / (m0 * c00 + m1 * c01 + m2 * c02);

    sM[0] = c00 * idet;
    sM[1] = -(m1 * m8 - m2 * m7) * idet;
    sM[2] =  (m1 * m5 - m2 * m4) * idet;
    sM[3] = c01 * idet;
    sM[4] =  (m0 * m8 - m2 * m6) * idet;
    sM[5] = -(m0 * m5 - m2 * m3) * idet;
    sM[6] = c02 * idet;
    sM[7] = -(m0 * m7 - m1 * m6) * idet;
    sM[8] =  (m0 * m4 - m1 * m3) * idet;
}

// ---------------------------------------------------------------------------
// Setup (R10 form): light mask (x0.85) + moire (x0.15); PDL trigger at top.
// ---------------------------------------------------------------------------
__global__ void setup_kernel(const float* __restrict__ ab,
                             const float* __restrict__ centers,
                             const int* __restrict__ cflag,
                             const int* __restrict__ direction,
                             const int* __restrict__ light_xy,
                             const int* __restrict__ theta) {
    cudaTriggerProgrammaticLaunchCompletion();

    int idx = blockIdx.x * blockDim.x + threadIdx.x;
    int i = idx / WW;   // row
    int j = idx % WW;   // col

    float a = ab[0], bb = ab[1];
    float L;
    if (cflag[0] == 0) {
        int k = direction[0] - 1;
        int t = (k == 0) ? i : (k == 1) ? j : (k == 2) ? (HH - 1 - i) : (WW - 1 - j);
        L = -((bb - a) / (float)(HH - 1)) * ((float)t - (float)WW) + a;
    } else {
        float x = (float)light_xy[0], y = (float)light_xy[1];
        float d0 = sqrtf(x * x + y * y);
        float d1 = sqrtf((x - 255.f) * (x - 255.f) + y * y);
        float d2 = sqrtf(x * x + (y - 255.f) * (y - 255.f));
        float d3 = sqrtf((x - 512.f) * (x - 512.f) + (y - 512.f) * (y - 512.f));
        float ml = fmaxf(fmaxf(d0, d1), fmaxf(d2, d3));
        float dx = (float)i - x, dy = (float)j - y;
        float dist = sqrtf(dx * dx + dy * dy);
        L = dist / ml * (a - bb) + bb;
    }
    g_A[idx] = L * 0.85f;

    const float TWO_PI = 6.283185307179586f;
    float xg = (float)(i + 1), yg = (float)(j + 1);
    #pragma unroll
    for (int k = 0; k < 3; k++) {
        float cx = centers[k * 2 + 0], cy = centers[k * 2 + 1];
        float th = (float)theta[k] * 0.017453292519943295f;
        float cth = __cosf(th), sth = __sinf(th);
        float dx = xg - cx, dy = yg - cy;
        float dist = sqrtf(dx * dx + dy * dy);
        float f1 = dist - floorf(dist);
        float t2 = cth * xg + sth * yg;
        float f2 = t2 - floorf(t2);
        float z1 = 0.5f + 0.5f * __cosf(TWO_PI * f1);
        float z2 = 0.5f + 0.5f * __cosf(TWO_PI * f2);
        g_Z[k * HW + idx] = fminf(z1, z2) * 0.15f;
    }
}

// ---------------------------------------------------------------------------
// Fused warp + blend, pair-gather, no p-loop. Block = 256 threads = one
// (b, y) row; thread t owns pixels 2t, 2t+1. Homography solved once per
// block (thread 0 -> smem). Perspective divide via rcp.approx (MUFU).
// ---------------------------------------------------------------------------
__global__ void __launch_bounds__(256) main_kernel(const float* __restrict__ img,
                                                   const float* __restrict__ noise,
                                                   const float* __restrict__ dst_off,
                                                   float* __restrict__ out) {
    __shared__ float sM[9];

    int b = blockIdx.z;
    int y = blockIdx.y;
    int tid = threadIdx.x;
    int x = 2 * tid;

    if (tid == 0) solve_one_thread(dst_off, b, sM);
    __syncthreads();

    float m0 = sM[0], m1 = sM[1], m2 = sM[2];
    float m3 = sM[3], m4 = sM[4], m5 = sM[5];
    float m6 = sM[6], m7 = sM[7], m8 = sM[8];

    float fy = (float)y;
    float cA = m1 * fy + m2;
    float cB = m4 * fy + m5;
    float cC = m7 * fy + m8;
    const float* base = img + (size_t)b * (3 * HW);

    float fx0 = (float)x, fx1 = (float)(x + 1);
    float den0 = m6 * fx0 + cC;
    float den1 = m6 * fx1 + cC;
    float inv0, inv1;
    asm("rcp.approx.f32 %0, %1;" : "=f"(inv0) : "f"(den0));
    asm("rcp.approx.f32 %0, %1;" : "=f"(inv1) : "f"(den1));
    float xs0 = (m0 * fx0 + cA) * inv0;
    float ys0 = (m3 * fx0 + cB) * inv0;
    float xs1 = (m0 * fx1 + cA) * inv1;
    float ys1 = (m3 * fx1 + cB) * inv1;

    float xf0 = floorf(xs0), yf0 = floorf(ys0);
    float xf1 = floorf(xs1), yf1 = floorf(ys1);
    float wx0 = xs0 - xf0, wy0 = ys0 - yf0;
    float wx1 = xs1 - xf1, wy1 = ys1 - yf1;
    int ix0 = (int)xf0, iy0 = (int)yf0;
    int ix1 = (int)xf1, iy1 = (int)yf1;

    bool adj = (iy1 == iy0) && (ix1 == ix0 + 1);
    bool interior = adj && ((unsigned)ix0 < (WW - 2)) && ((unsigned)iy0 < (HH - 1));

    float w000 = (1.f - wx0) * (1.f - wy0);
    float w010 = wx0 * (1.f - wy0);
    float w100 = (1.f - wx0) * wy0;
    float w110 = wx0 * wy0;
    float w001 = (1.f - wx1) * (1.f - wy1);
    float w011 = wx1 * (1.f - wy1);
    float w101 = (1.f - wx1) * wy1;
    float w111 = wx1 * wy1;

    int i0 = iy0 * WW + ix0;

    float rr[3][2];   // [ch][pix]

    if (interior) {
        #pragma unroll
        for (int ch = 0; ch < 3; ch++) {
            const float* pp = base + ch * HW + i0;
            float a0 = __ldg(pp);
            float a1 = __ldg(pp + 1);
            float a2 = __ldg(pp + 2);
            float b0 = __ldg(pp + WW);
            float b1 = __ldg(pp + WW + 1);
            float b2 = __ldg(pp + WW + 2);
            rr[ch][0] = a0 * w000 + a1 * w010 + b0 * w100 + b1 * w110;
            rr[ch][1] = a1 * w001 + a2 * w011 + b1 * w101 + b2 * w111;
        }
    } else {
        bool vy0 = ((unsigned)iy0 < HH);
        bool vy1 = ((unsigned)(iy0 + 1) < HH);
        bool vxa = ((unsigned)ix0 < WW);
        bool vxb = ((unsigned)(ix0 + 1) < WW);
        bool gy0 = ((unsigned)iy1 < HH);
        bool gy1 = ((unsigned)(iy1 + 1) < HH);
        bool gxa = ((unsigned)ix1 < WW);
        bool gxb = ((unsigned)(ix1 + 1) < WW);
        int i1 = iy1 * WW + ix1;
        bool p00 = vxa && vy0, p01 = vxb && vy0;
        bool p10 = vxa && vy1, p11 = vxb && vy1;
        bool q00 = gxa && gy0, q01 = gxb && gy0;
        bool q10 = gxa && gy1, q11 = gxb && gy1;
        #pragma unroll
        for (int ch = 0; ch < 3; ch++) {
            const float* pp = base + ch * HW + i0;
            const float* qq = base + ch * HW + i1;
            float v00 = p00 ? __ldg(pp)          : 0.f;
            float v01 = p01 ? __ldg(pp + 1)      : 0.f;
            float v10 = p10 ? __ldg(pp + WW)     : 0.f;
            float v11 = p11 ? __ldg(pp + WW + 1) : 0.f;
            float u00 = q00 ? __ldg(qq)          : 0.f;
            float u01 = q01 ? __ldg(qq + 1)      : 0.f;
            float u10 = q10 ? __ldg(qq + WW)     : 0.f;
            float u11 = q11 ? __ldg(qq + WW + 1) : 0.f;
            rr[ch][0] = v00 * w000 + v01 * w010 + v10 * w100 + v11 * w110;
            rr[ch][1] = u00 * w001 + u01 * w011 + u10 * w101 + u11 * w111;
        }
    }

    // noise prefetch (independent of setup) — hides under the PDL wait
    size_t rowoff = (size_t)(b * 3) * HW + (size_t)y * WW;
    float2 n0 = __ldcs((const float2*)(noise + rowoff + x));
    float2 n1 = __ldcs((const float2*)(noise + rowoff + HW + x));
    float2 n2 = __ldcs((const float2*)(noise + rowoff + 2 * HW + x));

    cudaGridDependencySynchronize();   // g_A / g_Z now visible

    const float kn = 0.031622776601683794f;  // sqrt(0.001)
    size_t prow = (size_t)y * WW + x;

    float2 av = *(const float2*)(g_A + prow);
    float2 z0 = *(const float2*)(g_Z + prow);
    float2 z1 = *(const float2*)(g_Z + HW + prow);
    float2 z2 = *(const float2*)(g_Z + 2 * HW + prow);

    float2 ov;
    ov.x = rr[0][0] * av.x + z0.x + kn * n0.x;
    ov.y = rr[0][1] * av.y + z0.y + kn * n0.y;
    __stcs((float2*)(out + rowoff + x), ov);
    ov.x = rr[1][0] * av.x + z1.x + kn * n1.x;
    ov.y = rr[1][1] * av.y + z1.y + kn * n1.y;
    __stcs((float2*)(out + rowoff + HW + x), ov);
    ov.x = rr[2][0] * av.x + z2.x + kn * n2.x;
    ov.y = rr[2][1] * av.y + z2.y + kn * n2.y;
    __stcs((float2*)(out + rowoff + 2 * HW + x), ov);
}

// ---------------------------------------------------------------------------
extern "C" void kernel_launch(void* const* d_in, const int* in_sizes, int n_in,
                              void* d_out, int out_size) {
    const float* image    = (const float*)d_in[0];
    const float* dst_off  = (const float*)d_in[1];
    const float* ab       = (const float*)d_in[2];
    const float* centers  = (const float*)d_in[3];
    const float* noise    = (const float*)d_in[4];
    const int*   c        = (const int*)d_in[5];
    const int*   direction= (const int*)d_in[6];
    const int*   light_xy = (const int*)d_in[7];
    const int*   theta    = (const int*)d_in[8];
    float* out = (float*)d_out;

    setup_kernel<<<HW / 256, 256>>>(ab, centers, c, direction, light_xy, theta);

    cudaLaunchConfig_t cfg = {};
    cfg.gridDim = dim3(1, HH, BN);
    cfg.blockDim = dim3(256, 1, 1);
    cfg.dynamicSmemBytes = 0;
    cfg.stream = 0;
    cudaLaunchAttribute attr[1];
    attr[0].id = cudaLaunchAttributeProgrammaticStreamSerialization;
    attr[0].val.programmaticStreamSerializationAllowed = 1;
    cfg.attrs = attr;
    cfg.numAttrs = 1;
    cudaLaunchKernelEx(&cfg, main_kernel, image, noise, dst_off, out);
}